// round 1
// baseline (speedup 1.0000x reference)
#include <cuda_runtime.h>

#define NB 64
#define TT 100
#define NN 25
#define VV 128
#define CC 128
#define EE 64
#define NG (NB*TT)
#define XSTR 132              // padded row stride for Xs/Vs (bank-conflict-free broadcasts)
#define CNT ((float)(NB*NN*CC))

__device__ float g_A2[NN*NN];
__device__ float g_rA[NN];
__device__ float g_b1w2[CC];
__device__ float g_W12[VV*CC];
__device__ float g_stats[2*TT];
__device__ float g_scale[TT];
__device__ float g_shift[TT];

typedef unsigned long long u64;

__device__ __forceinline__ u64 pk2(float v){
    u64 r; unsigned u = __float_as_uint(v);
    asm("mov.b64 %0, {%1, %1};" : "=l"(r) : "r"(u));
    return r;
}
__device__ __forceinline__ void ffma2(u64 &d, u64 a, u64 b){
    asm("fma.rn.f32x2 %0, %1, %2, %0;" : "+l"(d) : "l"(a), "l"(b));
}
__device__ __forceinline__ void upk(u64 v, float &lo, float &hi){
    unsigned a,b; asm("mov.b64 {%0, %1}, %2;" : "=r"(a), "=r"(b) : "l"(v));
    lo = __uint_as_float(a); hi = __uint_as_float(b);
}

// ---------------------------------------------------------------------------
// Prep: build normalized adjacency A (self-loops + sym norm), A2=A@A, rowsum,
// b1^T W2, and zero the stats accumulators. Auto-detect int64 vs int32 edges.
// ---------------------------------------------------------------------------
__global__ void prep_k(const int* __restrict__ ei,
                       const float* __restrict__ W2,
                       const float* __restrict__ b1){
    __shared__ float A[NN*NN];
    int tid = threadIdx.x;
    if (tid == 0){
        // int64 layout would be [v,0,v,0,...] in the first 128 int32 words
        bool is64 = true;
        for (int i = 0; i < 64; i++){
            if (ei[2*i+1] != 0 || (unsigned)ei[2*i] >= (unsigned)NN){ is64 = false; break; }
        }
        float deg[NN], dis[NN];
        for (int n = 0; n < NN; n++) deg[n] = 1.0f;          // self-loops
        for (int e = 0; e < EE; e++){
            int t = is64 ? ei[2*(EE+e)] : ei[EE+e];
            deg[t] += 1.0f;
        }
        for (int n = 0; n < NN; n++) dis[n] = rsqrtf(deg[n]);
        for (int i = 0; i < NN*NN; i++) A[i] = 0.0f;
        for (int e = 0; e < EE; e++){
            int s = is64 ? ei[2*e]        : ei[e];
            int t = is64 ? ei[2*(EE+e)]   : ei[EE+e];
            A[t*NN+s] += dis[s]*dis[t];
        }
        for (int n = 0; n < NN; n++) A[n*NN+n] += dis[n]*dis[n];
    }
    __syncthreads();
    for (int idx = tid; idx < NN*NN; idx += blockDim.x){
        int n = idx / NN, m = idx % NN;
        float s = 0.0f;
        #pragma unroll
        for (int j = 0; j < NN; j++) s += A[n*NN+j]*A[j*NN+m];
        g_A2[idx] = s;
    }
    if (tid < NN){
        float s = 0.0f;
        #pragma unroll
        for (int m = 0; m < NN; m++) s += A[tid*NN+m];
        g_rA[tid] = s;
    }
    if (tid < CC){
        float s = 0.0f;
        for (int k = 0; k < CC; k++) s += b1[k]*W2[k*CC+tid];
        g_b1w2[tid] = s;
    }
    if (tid < 2*TT) g_stats[tid] = 0.0f;
}

// W12 = W1 @ W2 (128x128), one row per block
__global__ void w12_k(const float* __restrict__ W1, const float* __restrict__ W2){
    __shared__ float row[CC];
    int i = blockIdx.x;
    row[threadIdx.x] = W1[i*CC + threadIdx.x];
    __syncthreads();
    int c = threadIdx.x;
    float s = 0.0f;
    #pragma unroll 8
    for (int j = 0; j < CC; j++) s += row[j]*W2[j*CC+c];
    g_W12[i*CC+c] = s;
}

// ---------------------------------------------------------------------------
// Main: per graph g,  Z = A2 @ (X @ W12) + bias,  written to out (scratch),
// while accumulating per-t sum / sumsq for BatchNorm.
// 128 threads/block: oct = tid&15 owns 8 columns, rg = tid>>4 owns rows
// {rg, rg+8, rg+16, (rg==0?24:dup)}. FFMA2 with 4x8 register blocking.
// ---------------------------------------------------------------------------
__global__ void gcn_k(const float* __restrict__ x,
                      const float* __restrict__ b2g,
                      float* __restrict__ out){
    extern __shared__ float sm[];
    float* ws  = sm;                    // 128*128
    float* Xs  = ws  + VV*CC;           // 25*132
    float* Vs  = Xs  + NN*XSTR;         // 25*132
    float* A2s = Vs  + NN*XSTR;         // 625
    float* rAs = A2s + NN*NN;           // 25
    float* bws = rAs + NN;              // 128
    float* b2s = bws + CC;              // 128

    const int tid = threadIdx.x;

    for (int i = tid; i < (VV*CC)/4; i += 128)
        ((float4*)ws)[i] = ((const float4*)g_W12)[i];
    for (int i = tid; i < NN*NN; i += 128) A2s[i] = g_A2[i];
    if (tid < NN) rAs[tid] = g_rA[tid];
    bws[tid] = g_b1w2[tid];
    b2s[tid] = b2g[tid];
    __syncthreads();

    const int oct = tid & 15;
    const int rg  = tid >> 4;
    const int c0  = oct << 3;
    const int nr0 = rg, nr1 = rg + 8, nr2 = rg + 16;
    const int nr3 = (rg == 0) ? 24 : rg;     // dup for rg>0, never stored
    const bool v3 = (rg == 0);
    const int nr[4] = {nr0, nr1, nr2, nr3};

    for (int g = blockIdx.x; g < NG; g += gridDim.x){
        // ---- load X tile (padded stride) ----
        const float4* xp = (const float4*)(x + (size_t)g*(NN*CC));
        for (int i = tid; i < (NN*CC)/4; i += 128){
            int row = i >> 5, col4 = i & 31;
            ((float4*)(Xs + row*XSTR))[col4] = xp[i];
        }
        __syncthreads();

        // ---- stage 1: Vs = Xs @ ws  (K = 128) ----
        {
            u64 acc[4][4];
            #pragma unroll
            for (int j = 0; j < 4; j++)
                #pragma unroll
                for (int p = 0; p < 4; p++) acc[j][p] = 0ull;

            #pragma unroll 4
            for (int k = 0; k < VV; k++){
                const float* wr = ws + (k << 7) + c0;
                ulonglong2 wa = *(const ulonglong2*)wr;
                ulonglong2 wb = *(const ulonglong2*)(wr + 4);
                u64 w4x = wa.x, w4y = wa.y, w4z = wb.x, w4w = wb.y;
                #pragma unroll
                for (int j = 0; j < 4; j++){
                    u64 u = pk2(Xs[nr[j]*XSTR + k]);
                    ffma2(acc[j][0], u, w4x);
                    ffma2(acc[j][1], u, w4y);
                    ffma2(acc[j][2], u, w4z);
                    ffma2(acc[j][3], u, w4w);
                }
            }
            #pragma unroll
            for (int j = 0; j < 4; j++){
                if (j < 3 || v3){
                    ulonglong2* vp = (ulonglong2*)(Vs + nr[j]*XSTR + c0);
                    ulonglong2 t0; t0.x = acc[j][0]; t0.y = acc[j][1];
                    ulonglong2 t1; t1.x = acc[j][2]; t1.y = acc[j][3];
                    vp[0] = t0; vp[1] = t1;
                }
            }
        }
        __syncthreads();

        // ---- stage 2: Z = A2 @ Vs + bias  (K = 25) ----
        {
            u64 acc[4][4];
            #pragma unroll
            for (int j = 0; j < 4; j++)
                #pragma unroll
                for (int p = 0; p < 4; p++) acc[j][p] = 0ull;

            #pragma unroll 5
            for (int m = 0; m < NN; m++){
                const float* vr = Vs + m*XSTR + c0;
                ulonglong2 wa = *(const ulonglong2*)vr;
                ulonglong2 wb = *(const ulonglong2*)(vr + 4);
                u64 w4x = wa.x, w4y = wa.y, w4z = wb.x, w4w = wb.y;
                #pragma unroll
                for (int j = 0; j < 4; j++){
                    u64 u = pk2(A2s[nr[j]*NN + m]);
                    ffma2(acc[j][0], u, w4x);
                    ffma2(acc[j][1], u, w4y);
                    ffma2(acc[j][2], u, w4z);
                    ffma2(acc[j][3], u, w4w);
                }
            }

            float* zp = out + (size_t)g*(NN*CC);
            float ls = 0.0f, lss = 0.0f;
            #pragma unroll
            for (int j = 0; j < 4; j++){
                if (j < 3 || v3){
                    int n = nr[j];
                    float r = rAs[n];
                    float o[8];
                    upk(acc[j][0], o[0], o[1]);
                    upk(acc[j][1], o[2], o[3]);
                    upk(acc[j][2], o[4], o[5]);
                    upk(acc[j][3], o[6], o[7]);
                    #pragma unroll
                    for (int p = 0; p < 8; p++){
                        float v = fmaf(r, bws[c0+p], o[p]) + b2s[c0+p];
                        o[p] = v;
                        ls  += v;
                        lss  = fmaf(v, v, lss);
                    }
                    float4* op = (float4*)(zp + n*CC + c0);
                    op[0] = make_float4(o[0], o[1], o[2], o[3]);
                    op[1] = make_float4(o[4], o[5], o[6], o[7]);
                }
            }
            // per-warp reduce, 2 atomics per warp per graph
            #pragma unroll
            for (int s = 16; s; s >>= 1){
                ls  += __shfl_xor_sync(0xffffffffu, ls,  s);
                lss += __shfl_xor_sync(0xffffffffu, lss, s);
            }
            if ((tid & 31) == 0){
                int t = g % TT;
                atomicAdd(&g_stats[t],      ls);
                atomicAdd(&g_stats[TT + t], lss);
            }
        }
        __syncthreads();   // Vs/Xs safe for next graph
    }
}

// stats -> per-t scale/shift (fold gamma/beta)
__global__ void fin_k(const float* __restrict__ gamma, const float* __restrict__ beta){
    int t = threadIdx.x;
    if (t < TT){
        float mean = g_stats[t] / CNT;
        float var  = g_stats[TT + t] / CNT - mean*mean;
        float sc   = rsqrtf(var + 1e-5f) * gamma[t];
        g_scale[t] = sc;
        g_shift[t] = beta[t] - mean*sc;
    }
}

// in-place BN + ReLU, 16 floats per thread-iter (t constant within a group)
__global__ void bn_k(float* __restrict__ out){
    const int total16 = (NB*TT*NN*CC)/16;   // 1,280,000
    int stride = gridDim.x * blockDim.x;
    for (int i = blockIdx.x*blockDim.x + threadIdx.x; i < total16; i += stride){
        int t = (i / 200) % TT;             // 200 = N*C/16 groups per (b,t)
        float sc = g_scale[t], sh = g_shift[t];
        float4* p = (float4*)out + (size_t)i*4;
        #pragma unroll
        for (int q = 0; q < 4; q++){
            float4 v = p[q];
            v.x = fmaxf(fmaf(v.x, sc, sh), 0.0f);
            v.y = fmaxf(fmaf(v.y, sc, sh), 0.0f);
            v.z = fmaxf(fmaf(v.z, sc, sh), 0.0f);
            v.w = fmaxf(fmaf(v.w, sc, sh), 0.0f);
            p[q] = v;
        }
    }
}

extern "C" void kernel_launch(void* const* d_in, const int* in_sizes, int n_in,
                              void* d_out, int out_size){
    const float* x  = (const float*)d_in[0];
    const int*   ei = (const int*)  d_in[1];
    const float* W1 = (const float*)d_in[2];
    const float* b1 = (const float*)d_in[3];
    const float* W2 = (const float*)d_in[4];
    const float* b2 = (const float*)d_in[5];
    const float* ga = (const float*)d_in[6];
    const float* be = (const float*)d_in[7];
    float* out = (float*)d_out;

    int nsm = 148;
    cudaDeviceGetAttribute(&nsm, cudaDevAttrMultiProcessorCount, 0);

    const int smemB = (VV*CC + 2*NN*XSTR + NN*NN + NN + 2*CC) * (int)sizeof(float);
    cudaFuncSetAttribute(gcn_k, cudaFuncAttributeMaxDynamicSharedMemorySize, smemB);

    prep_k<<<1, 256>>>(ei, W2, b1);
    w12_k<<<VV, CC>>>(W1, W2);
    gcn_k<<<nsm*2, 128, smemB>>>(x, b2, out);
    fin_k<<<1, 128>>>(ga, be);
    bn_k<<<nsm*8, 256>>>(out);
}

// round 4
// speedup vs baseline: 1.1377x; 1.1377x over previous
#include <cuda_runtime.h>

#define NB 64
#define TT 100
#define NN 25
#define VV 128
#define CC 128
#define EE 64
#define NG (NB*TT)
#define XSTR 132              // padded row stride (conflict-free cross-halfwarp broadcasts)
#define CNT ((float)(NB*NN*CC))

__device__ float g_A2[NN*NN];
__device__ float g_rA[NN];
__device__ float g_b1w2[CC];
__device__ float g_W12[VV*CC];
__device__ float g_stats[2*TT];

typedef unsigned long long u64;

__device__ __forceinline__ u64 pk2(float v){
    u64 r; unsigned u = __float_as_uint(v);
    asm("mov.b64 %0, {%1, %1};" : "=l"(r) : "r"(u));
    return r;
}
__device__ __forceinline__ void ffma2(u64 &d, u64 a, u64 b){
    asm("fma.rn.f32x2 %0, %1, %2, %0;" : "+l"(d) : "l"(a), "l"(b));
}
__device__ __forceinline__ void upk(u64 v, float &lo, float &hi){
    unsigned a,b; asm("mov.b64 {%0, %1}, %2;" : "=r"(a), "=r"(b) : "l"(v));
    lo = __uint_as_float(a); hi = __uint_as_float(b);
}

// ---------------------------------------------------------------------------
// Fused prep: block 0 builds normalized adjacency A (self-loops + sym norm),
// A2 = A@A, rowsum(A), b1^T W2, and zeroes ALL stats accumulators (strided
// loop — this was the replay-divergence bug when blockDim < 2*TT).
// All 128 blocks compute one row of W12 = W1 @ W2.
// Edge dtype (int64 vs int32) auto-detected.
// ---------------------------------------------------------------------------
__global__ void prep_k(const int* __restrict__ ei,
                       const float* __restrict__ W1,
                       const float* __restrict__ W2,
                       const float* __restrict__ b1){
    __shared__ float A[NN*NN];
    __shared__ float row[CC];
    const int tid = threadIdx.x;
    const int bi  = blockIdx.x;

    // ---- W12 row bi (all blocks) ----
    row[tid] = W1[bi*CC + tid];
    __syncthreads();
    {
        float s = 0.0f;
        #pragma unroll 8
        for (int j = 0; j < CC; j++) s += row[j]*W2[j*CC+tid];
        g_W12[bi*CC+tid] = s;
    }

    if (bi != 0) return;

    // ---- zero stats (every slot, every call — idempotence across replays) ----
    for (int t = tid; t < 2*TT; t += blockDim.x) g_stats[t] = 0.0f;

    // ---- adjacency (block 0) ----
    if (tid == 0){
        bool is64 = true;
        for (int i = 0; i < 64; i++){
            if (ei[2*i+1] != 0 || (unsigned)ei[2*i] >= (unsigned)NN){ is64 = false; break; }
        }
        float deg[NN], dis[NN];
        for (int n = 0; n < NN; n++) deg[n] = 1.0f;          // self-loops
        for (int e = 0; e < EE; e++){
            int t = is64 ? ei[2*(EE+e)] : ei[EE+e];
            deg[t] += 1.0f;
        }
        for (int n = 0; n < NN; n++) dis[n] = rsqrtf(deg[n]);
        for (int i = 0; i < NN*NN; i++) A[i] = 0.0f;
        for (int e = 0; e < EE; e++){
            int s = is64 ? ei[2*e]      : ei[e];
            int t = is64 ? ei[2*(EE+e)] : ei[EE+e];
            A[t*NN+s] += dis[s]*dis[t];
        }
        for (int n = 0; n < NN; n++) A[n*NN+n] += dis[n]*dis[n];
    }
    __syncthreads();
    for (int idx = tid; idx < NN*NN; idx += blockDim.x){
        int n = idx / NN, m = idx % NN;
        float s = 0.0f;
        #pragma unroll
        for (int j = 0; j < NN; j++) s += A[n*NN+j]*A[j*NN+m];
        g_A2[idx] = s;
    }
    if (tid < NN){
        float s = 0.0f;
        #pragma unroll
        for (int m = 0; m < NN; m++) s += A[tid*NN+m];
        g_rA[tid] = s;
    }
    if (tid < CC){
        float s = 0.0f;
        for (int k = 0; k < CC; k++) s += b1[k]*W2[k*CC+tid];
        g_b1w2[tid] = s;
    }
}

// ---------------------------------------------------------------------------
// Main: per graph g,  Z = A2 @ (X @ W12) + bias -> out (scratch), plus per-t
// sum/sumsq accumulation.  256 threads/block = 2 independent graphs sharing
// the 64KB W12 smem tile; the X tile is reused as the V tile (accumulators
// stay in registers across the handoff).  2 blocks/SM -> 16 warps/SM.
// Within a 128-thread half: oct = tid&15 owns 8 columns, rg = tid>>4 owns
// rows {rg, rg+8, rg+16, (rg==0?24)}.  FFMA2 4x8 register blocking.
// ---------------------------------------------------------------------------
__global__ __launch_bounds__(256, 2)
void gcn_k(const float* __restrict__ x,
           const float* __restrict__ b2g,
           float* __restrict__ out,
           int gbase, int gcount){
    extern __shared__ float sm[];
    float* ws  = sm;                    // 128*128
    float* XV  = ws  + VV*CC;           // 2 * 25*132  (X tile, then V tile)
    float* A2s = XV  + 2*NN*XSTR;       // 625
    float* rAs = A2s + NN*NN;           // 32
    float* bws = rAs + 32;              // 128
    float* b2s = bws + CC;              // 128

    const int tid  = threadIdx.x;
    const int half = tid >> 7;
    const int tid1 = tid & 127;

    for (int i = tid; i < (VV*CC)/4; i += 256)
        ((float4*)ws)[i] = ((const float4*)g_W12)[i];
    for (int i = tid; i < NN*NN; i += 256) A2s[i] = g_A2[i];
    if (tid < NN)  rAs[tid] = g_rA[tid];
    if (tid < CC)  bws[tid] = g_b1w2[tid];
    if (tid >= CC && tid < 2*CC) b2s[tid-CC] = b2g[tid-CC];
    __syncthreads();

    float* Xs = XV + half*(NN*XSTR);

    const int oct = tid1 & 15;
    const int rg  = tid1 >> 4;
    const int c0  = oct << 3;
    const int nr0 = rg, nr1 = rg + 8, nr2 = rg + 16;
    const int nr3 = (rg == 0) ? 24 : rg;     // dup for rg>0, never stored
    const bool v3 = (rg == 0);
    const int nr[4] = {nr0, nr1, nr2, nr3};

    const int npair = gcount >> 1;
    for (int p = blockIdx.x; p < npair; p += gridDim.x){
        const int g = gbase + p*2 + half;

        // ---- load X tile (padded stride) ----
        const float4* xp = (const float4*)(x + (size_t)g*(NN*CC));
        for (int i = tid1; i < (NN*CC)/4; i += 128){
            int row = i >> 5, col4 = i & 31;
            ((float4*)(Xs + row*XSTR))[col4] = xp[i];
        }
        __syncthreads();

        // ---- stage 1: V = X @ W12  (K = 128), acc in regs ----
        u64 acc[4][4];
        #pragma unroll
        for (int j = 0; j < 4; j++)
            #pragma unroll
            for (int q = 0; q < 4; q++) acc[j][q] = 0ull;

        #pragma unroll 4
        for (int k = 0; k < VV; k++){
            const float* wr = ws + (k << 7) + c0;
            ulonglong2 wa = *(const ulonglong2*)wr;
            ulonglong2 wb = *(const ulonglong2*)(wr + 4);
            u64 w4x = wa.x, w4y = wa.y, w4z = wb.x, w4w = wb.y;
            #pragma unroll
            for (int j = 0; j < 4; j++){
                u64 u = pk2(Xs[nr[j]*XSTR + k]);
                ffma2(acc[j][0], u, w4x);
                ffma2(acc[j][1], u, w4y);
                ffma2(acc[j][2], u, w4z);
                ffma2(acc[j][3], u, w4w);
            }
        }
        __syncthreads();   // all X reads done -> reuse buffer as V

        #pragma unroll
        for (int j = 0; j < 4; j++){
            if (j < 3 || v3){
                ulonglong2* vp = (ulonglong2*)(Xs + nr[j]*XSTR + c0);
                ulonglong2 t0; t0.x = acc[j][0]; t0.y = acc[j][1];
                ulonglong2 t1; t1.x = acc[j][2]; t1.y = acc[j][3];
                vp[0] = t0; vp[1] = t1;
            }
        }
        __syncthreads();

        // ---- stage 2: Z = A2 @ V + bias  (K = 25) ----
        #pragma unroll
        for (int j = 0; j < 4; j++)
            #pragma unroll
            for (int q = 0; q < 4; q++) acc[j][q] = 0ull;

        #pragma unroll 5
        for (int m = 0; m < NN; m++){
            const float* vr = Xs + m*XSTR + c0;
            ulonglong2 wa = *(const ulonglong2*)vr;
            ulonglong2 wb = *(const ulonglong2*)(vr + 4);
            u64 w4x = wa.x, w4y = wa.y, w4z = wb.x, w4w = wb.y;
            #pragma unroll
            for (int j = 0; j < 4; j++){
                u64 u = pk2(A2s[nr[j]*NN + m]);
                ffma2(acc[j][0], u, w4x);
                ffma2(acc[j][1], u, w4y);
                ffma2(acc[j][2], u, w4z);
                ffma2(acc[j][3], u, w4w);
            }
        }

        float* zp = out + (size_t)g*(NN*CC);
        float ls = 0.0f, lss = 0.0f;
        #pragma unroll
        for (int j = 0; j < 4; j++){
            if (j < 3 || v3){
                int n = nr[j];
                float r = rAs[n];
                float o[8];
                upk(acc[j][0], o[0], o[1]);
                upk(acc[j][1], o[2], o[3]);
                upk(acc[j][2], o[4], o[5]);
                upk(acc[j][3], o[6], o[7]);
                #pragma unroll
                for (int q = 0; q < 8; q++){
                    float v = fmaf(r, bws[c0+q], o[q]) + b2s[c0+q];
                    o[q] = v;
                    ls  += v;
                    lss  = fmaf(v, v, lss);
                }
                float4* op = (float4*)(zp + n*CC + c0);
                op[0] = make_float4(o[0], o[1], o[2], o[3]);
                op[1] = make_float4(o[4], o[5], o[6], o[7]);
            }
        }
        #pragma unroll
        for (int s = 16; s; s >>= 1){
            ls  += __shfl_xor_sync(0xffffffffu, ls,  s);
            lss += __shfl_xor_sync(0xffffffffu, lss, s);
        }
        if ((tid1 & 31) == 0){
            int t = g % TT;
            atomicAdd(&g_stats[t],      ls);
            atomicAdd(&g_stats[TT + t], lss);
        }
        __syncthreads();   // V reads done before next graph's X staging
    }
}

// BN finalize (per-block redundant, cheap) + in-place BN + ReLU.
__global__ void bn_k(const float* __restrict__ gamma,
                     const float* __restrict__ beta,
                     float* __restrict__ out){
    __shared__ float sc[TT], sh[TT];
    for (int t = threadIdx.x; t < TT; t += blockDim.x){
        float mean = g_stats[t] / CNT;
        float var  = g_stats[TT + t] / CNT - mean*mean;
        float s    = rsqrtf(var + 1e-5f) * gamma[t];
        sc[t] = s;
        sh[t] = beta[t] - mean*s;
    }
    __syncthreads();

    const int total16 = (NB*TT*NN*CC)/16;   // 1,280,000
    int stride = gridDim.x * blockDim.x;
    for (int i = blockIdx.x*blockDim.x + threadIdx.x; i < total16; i += stride){
        int t = (i / 200) % TT;             // 200 = N*C/16 groups per (b,t)
        float s = sc[t], h = sh[t];
        float4* p = (float4*)out + (size_t)i*4;
        #pragma unroll
        for (int q = 0; q < 4; q++){
            float4 v = p[q];
            v.x = fmaxf(fmaf(v.x, s, h), 0.0f);
            v.y = fmaxf(fmaf(v.y, s, h), 0.0f);
            v.z = fmaxf(fmaf(v.z, s, h), 0.0f);
            v.w = fmaxf(fmaf(v.w, s, h), 0.0f);
            p[q] = v;
        }
    }
}

extern "C" void kernel_launch(void* const* d_in, const int* in_sizes, int n_in,
                              void* d_out, int out_size){
    const float* x  = (const float*)d_in[0];
    const int*   ei = (const int*)  d_in[1];
    const float* W1 = (const float*)d_in[2];
    const float* b1 = (const float*)d_in[3];
    const float* W2 = (const float*)d_in[4];
    const float* b2 = (const float*)d_in[5];
    const float* ga = (const float*)d_in[6];
    const float* be = (const float*)d_in[7];
    float* out = (float*)d_out;

    int nsm = 148;
    cudaDeviceGetAttribute(&nsm, cudaDevAttrMultiProcessorCount, 0);

    const int smemB = (VV*CC + 2*NN*XSTR + NN*NN + 32 + 2*CC) * (int)sizeof(float);
    cudaFuncSetAttribute(gcn_k, cudaFuncAttributeMaxDynamicSharedMemorySize, smemB);

    prep_k<<<CC, CC>>>(ei, W1, W2, b1);
    gcn_k<<<nsm*2, 256, smemB>>>(x, b2, out, 0,      NG/2);
    gcn_k<<<nsm*2, 256, smemB>>>(x, b2, out, NG/2,   NG/2);
    bn_k<<<nsm*8, 256>>>(ga, be, out);
}

// round 6
// speedup vs baseline: 1.6847x; 1.4808x over previous
#include <cuda_runtime.h>

#define NB 64
#define TT 100
#define NN 25
#define VV 128
#define CC 128
#define EE 64
#define NG (NB*TT)
#define GPT 5                 // graphs per tile
#define MR (GPT*NN)           // 125 rows per tile
#define NTILES (NG/GPT)       // 1280
#define XSTR 129              // X-tile stride: bank(r,k) = (r+k)%32 -> conflict-free A frags
#define VSTR 132              // V-tile stride: 16B-aligned rows for LDS.128
#define WS_F (VV*CC)          // 16384
#define XV_F 16512            // max(128*129, 125*132)
#define A2_F 640              // 625 padded to multiple of 4 -> downstream float4 alignment
#define CNT ((float)(NB*NN*CC))

__device__ float g_A2[NN*NN];
__device__ float g_rA[NN];
__device__ float g_b1w2[CC];
__device__ float g_W12[VV*CC];
__device__ float g_stats[2*TT];

typedef unsigned long long u64;

__device__ __forceinline__ u64 pk2(float v){
    u64 r; unsigned u = __float_as_uint(v);
    asm("mov.b64 %0, {%1, %1};" : "=l"(r) : "r"(u));
    return r;
}
__device__ __forceinline__ void ffma2(u64 &d, u64 a, u64 b){
    asm("fma.rn.f32x2 %0, %1, %2, %0;" : "+l"(d) : "l"(a), "l"(b));
}
__device__ __forceinline__ void upk(u64 v, float &lo, float &hi){
    unsigned a,b; asm("mov.b64 {%0, %1}, %2;" : "=r"(a), "=r"(b) : "l"(v));
    lo = __uint_as_float(a); hi = __uint_as_float(b);
}

// ---------------------------------------------------------------------------
// Fused prep: block 0 builds normalized adjacency A (self-loops + sym norm),
// A2=A@A, rowsum(A), b1^T W2, zeroes ALL stats (strided — replay idempotence).
// All 128 blocks compute one row of W12 = W1 @ W2.  Edge dtype auto-detected.
// ---------------------------------------------------------------------------
__global__ void prep_k(const int* __restrict__ ei,
                       const float* __restrict__ W1,
                       const float* __restrict__ W2,
                       const float* __restrict__ b1){
    __shared__ float A[NN*NN];
    __shared__ float row[CC];
    const int tid = threadIdx.x;
    const int bi  = blockIdx.x;

    row[tid] = W1[bi*CC + tid];
    __syncthreads();
    {
        float s = 0.0f;
        #pragma unroll 8
        for (int j = 0; j < CC; j++) s += row[j]*W2[j*CC+tid];
        g_W12[bi*CC+tid] = s;
    }

    if (bi != 0) return;

    for (int t = tid; t < 2*TT; t += blockDim.x) g_stats[t] = 0.0f;

    if (tid == 0){
        bool is64 = true;
        for (int i = 0; i < 64; i++){
            if (ei[2*i+1] != 0 || (unsigned)ei[2*i] >= (unsigned)NN){ is64 = false; break; }
        }
        float deg[NN], dis[NN];
        for (int n = 0; n < NN; n++) deg[n] = 1.0f;          // self-loops
        for (int e = 0; e < EE; e++){
            int t = is64 ? ei[2*(EE+e)] : ei[EE+e];
            deg[t] += 1.0f;
        }
        for (int n = 0; n < NN; n++) dis[n] = rsqrtf(deg[n]);
        for (int i = 0; i < NN*NN; i++) A[i] = 0.0f;
        for (int e = 0; e < EE; e++){
            int s = is64 ? ei[2*e]      : ei[e];
            int t = is64 ? ei[2*(EE+e)] : ei[EE+e];
            A[t*NN+s] += dis[s]*dis[t];
        }
        for (int n = 0; n < NN; n++) A[n*NN+n] += dis[n]*dis[n];
    }
    __syncthreads();
    for (int idx = tid; idx < NN*NN; idx += blockDim.x){
        int n = idx / NN, m = idx % NN;
        float s = 0.0f;
        #pragma unroll
        for (int j = 0; j < NN; j++) s += A[n*NN+j]*A[j*NN+m];
        g_A2[idx] = s;
    }
    if (tid < NN){
        float s = 0.0f;
        #pragma unroll
        for (int m = 0; m < NN; m++) s += A[tid*NN+m];
        g_rA[tid] = s;
    }
    if (tid < CC){
        float s = 0.0f;
        for (int k = 0; k < CC; k++) s += b1[k]*W2[k*CC+tid];
        g_b1w2[tid] = s;
    }
}

// ---------------------------------------------------------------------------
// Main persistent kernel.  Per tile = 5 graphs = 125 rows:
//   stage 1: V[125,128] = X[125,128] @ W12[128,128]  (8x8 register blocking,
//            X staged at stride 129 -> conflict-free LDS broadcasts,
//            W read via deduped LDS.128; fma-pipe-bound)
//   stage 2: per warp w<5: graph w:  Z = A2 @ V + rA(x)b1W2 + b2, 25 rows x
//            4 cols/lane; one V frag per m shared by all 25 rows.
//   stats:   per-graph sum/sumsq -> warp reduce -> 2 global atomics.
// 256 threads, 1 block/SM (134KB smem), W12/A2 loaded once per block.
// ---------------------------------------------------------------------------
__global__ __launch_bounds__(256, 1)
void gcn_k(const float* __restrict__ x,
           const float* __restrict__ b2g,
           float* __restrict__ out){
    extern __shared__ float sm[];
    float* ws  = sm;            // W12 [k][c], 128x128
    float* XV  = ws + WS_F;     // X tile (stride 129) then V tile (stride 132)
    float* A2s = XV + XV_F;     // 625 used, 640 reserved (alignment pad)
    float* rAs = A2s + A2_F;    // 32
    float* bws = rAs + 32;      // 128 (16B-aligned)
    float* b2s = bws + CC;      // 128 (16B-aligned)

    const int tid  = threadIdx.x;
    const int tc   = tid & 15;
    const int tr   = tid >> 4;
    const int c0   = tc << 3;
    const int lane = tid & 31;
    const int wid  = tid >> 5;

    for (int i = tid; i < WS_F/4; i += 256)
        ((float4*)ws)[i] = ((const float4*)g_W12)[i];
    for (int i = tid; i < NN*NN; i += 256) A2s[i] = g_A2[i];
    if (tid < NN) rAs[tid] = g_rA[tid];
    if (tid < CC) bws[tid] = g_b1w2[tid];
    else if (tid < 2*CC) b2s[tid-CC] = b2g[tid-CC];
    __syncthreads();

    for (int tile = blockIdx.x; tile < NTILES; tile += gridDim.x){
        // ---- stage X: 125x128 rows, stride-129 layout ----
        const float4* xp = (const float4*)(x + (size_t)tile*(MR*CC));
        for (int i = tid; i < (MR*CC)/4; i += 256){
            float4 v = xp[i];
            int row = i >> 5, cb = (i & 31) << 2;
            float* d = XV + row*XSTR + cb;
            d[0]=v.x; d[1]=v.y; d[2]=v.z; d[3]=v.w;
        }
        __syncthreads();

        // ---- stage 1: V = X @ W12  (rows 120..127 of the 8x8 tile may be
        //      garbage for tr=15; never stored) ----
        u64 acc[8][4];
        #pragma unroll
        for (int i = 0; i < 8; i++)
            #pragma unroll
            for (int q = 0; q < 4; q++) acc[i][q] = 0ull;

        #pragma unroll 4
        for (int k = 0; k < VV; k++){
            const float* wr = ws + (k << 7) + c0;
            ulonglong2 wa = *(const ulonglong2*)wr;
            ulonglong2 wb = *(const ulonglong2*)(wr + 4);
            float af[8];
            #pragma unroll
            for (int i = 0; i < 8; i++) af[i] = XV[(tr*8 + i)*XSTR + k];
            #pragma unroll
            for (int i = 0; i < 8; i++){
                u64 a = pk2(af[i]);
                ffma2(acc[i][0], a, wa.x);
                ffma2(acc[i][1], a, wa.y);
                ffma2(acc[i][2], a, wb.x);
                ffma2(acc[i][3], a, wb.y);
            }
        }
        __syncthreads();   // X fully consumed -> reuse buffer as V (stride 132)

        #pragma unroll
        for (int i = 0; i < 8; i++){
            int row = tr*8 + i;
            if (row < MR){
                ulonglong2* vp = (ulonglong2*)(XV + row*VSTR + c0);
                ulonglong2 t0; t0.x = acc[i][0]; t0.y = acc[i][1];
                ulonglong2 t1; t1.x = acc[i][2]; t1.y = acc[i][3];
                vp[0] = t0; vp[1] = t1;
            }
        }
        __syncthreads();

        // ---- stage 2: warps 0..4 each own one graph ----
        if (wid < GPT){
            const int g = tile*GPT + wid;
            u64 z[NN][2];
            #pragma unroll
            for (int n = 0; n < NN; n++){ z[n][0] = 0ull; z[n][1] = 0ull; }

            #pragma unroll 5
            for (int m = 0; m < NN; m++){
                ulonglong2 v = *(const ulonglong2*)(XV + (wid*NN + m)*VSTR + (lane << 2));
                #pragma unroll
                for (int n = 0; n < NN; n++){
                    u64 a = pk2(A2s[n*NN + m]);
                    ffma2(z[n][0], a, v.x);
                    ffma2(z[n][1], a, v.y);
                }
            }

            float4 bw = *(const float4*)(bws + (lane << 2));
            float4 bb = *(const float4*)(b2s + (lane << 2));
            float* zp = out + (size_t)g*(NN*CC) + (lane << 2);
            float ls = 0.0f, lss = 0.0f;
            #pragma unroll
            for (int n = 0; n < NN; n++){
                float r = rAs[n];
                float o0,o1,o2,o3;
                upk(z[n][0], o0, o1);
                upk(z[n][1], o2, o3);
                o0 = fmaf(r, bw.x, o0) + bb.x;
                o1 = fmaf(r, bw.y, o1) + bb.y;
                o2 = fmaf(r, bw.z, o2) + bb.z;
                o3 = fmaf(r, bw.w, o3) + bb.w;
                ls += o0 + o1 + o2 + o3;
                lss = fmaf(o0,o0, fmaf(o1,o1, fmaf(o2,o2, fmaf(o3,o3, lss))));
                *(float4*)(zp + n*CC) = make_float4(o0,o1,o2,o3);
            }
            #pragma unroll
            for (int s = 16; s; s >>= 1){
                ls  += __shfl_xor_sync(0xffffffffu, ls,  s);
                lss += __shfl_xor_sync(0xffffffffu, lss, s);
            }
            if (lane == 0){
                int t = g % TT;
                atomicAdd(&g_stats[t],      ls);
                atomicAdd(&g_stats[TT + t], lss);
            }
        }
        __syncthreads();   // V reads done before next tile's X staging
    }
}

// BN finalize (per-block redundant) + in-place BN + ReLU.
__global__ void bn_k(const float* __restrict__ gamma,
                     const float* __restrict__ beta,
                     float* __restrict__ out){
    __shared__ float sc[TT], sh[TT];
    for (int t = threadIdx.x; t < TT; t += blockDim.x){
        float mean = g_stats[t] / CNT;
        float var  = g_stats[TT + t] / CNT - mean*mean;
        float s    = rsqrtf(var + 1e-5f) * gamma[t];
        sc[t] = s;
        sh[t] = beta[t] - mean*s;
    }
    __syncthreads();

    const int total16 = (NB*TT*NN*CC)/16;   // 1,280,000
    int stride = gridDim.x * blockDim.x;
    for (int i = blockIdx.x*blockDim.x + threadIdx.x; i < total16; i += stride){
        int t = (i / 200) % TT;             // 200 = N*C/16 groups per (b,t)
        float s = sc[t], h = sh[t];
        float4* p = (float4*)out + (size_t)i*4;
        #pragma unroll
        for (int q = 0; q < 4; q++){
            float4 v = p[q];
            v.x = fmaxf(fmaf(v.x, s, h), 0.0f);
            v.y = fmaxf(fmaf(v.y, s, h), 0.0f);
            v.z = fmaxf(fmaf(v.z, s, h), 0.0f);
            v.w = fmaxf(fmaf(v.w, s, h), 0.0f);
            p[q] = v;
        }
    }
}

extern "C" void kernel_launch(void* const* d_in, const int* in_sizes, int n_in,
                              void* d_out, int out_size){
    const float* x  = (const float*)d_in[0];
    const int*   ei = (const int*)  d_in[1];
    const float* W1 = (const float*)d_in[2];
    const float* b1 = (const float*)d_in[3];
    const float* W2 = (const float*)d_in[4];
    const float* b2 = (const float*)d_in[5];
    const float* ga = (const float*)d_in[6];
    const float* be = (const float*)d_in[7];
    float* out = (float*)d_out;

    int nsm = 148;
    cudaDeviceGetAttribute(&nsm, cudaDevAttrMultiProcessorCount, 0);

    const int smemB = (WS_F + XV_F + A2_F + 32 + 2*CC) * (int)sizeof(float);
    cudaFuncSetAttribute(gcn_k, cudaFuncAttributeMaxDynamicSharedMemorySize, smemB);

    prep_k<<<CC, CC>>>(ei, W1, W2, b1);
    gcn_k<<<nsm, 256, smemB>>>(x, b2, out);
    bn_k<<<nsm*8, 256>>>(ga, be, out);
}